// round 5
// baseline (speedup 1.0000x reference)
#include <cuda_runtime.h>
#include <math_constants.h>

#define DD   128
#define HH   4
#define RNUM 2000
#define MAXM 768
#define NCPY 32
#define XST  132

// ---------------- scratch ----------------
__device__ float  g_a[HH * DD];
__device__ float  g_c[HH];
__device__ float  g_qf[DD];
__device__ int    g_cnt32[NCPY * RNUM];   // invariant: zero at entry (scan resets)
__device__ int    g_cur32[NCPY * RNUM];
__device__ int    g_deg[RNUM];            // invariant: zero at entry (scan resets)
__device__ int    g_starts[RNUM + 1];
__device__ float  g_dis[RNUM];
__device__ int    g_idx[1 << 20];
__device__ float4 g_e4[1 << 19];          // exp-scores per POI (8 MB)
__device__ float  g_Px[RNUM * HH * DD];
__device__ float  g_hg[RNUM * DD];

// ---------------- prep: folded q/a/c (1 block, 128 thr) — main stream ----------------
__global__ void k_prep(const float* __restrict__ S, const float* __restrict__ Wq,
                       const float* __restrict__ bq, const float* __restrict__ Wk,
                       const float* __restrict__ bk) {
    __shared__ float sS[DD], sqf[DD];
    int t = threadIdx.x;
    sS[t] = S[t];
    __syncthreads();
    {
        const float4* wr = (const float4*)(Wq + t * DD);
        const float4* sv = (const float4*)sS;
        float s = 0.f;
#pragma unroll
        for (int j = 0; j < 32; j++) {
            float4 w = wr[j], v = sv[j];
            s += w.x * v.x + w.y * v.y + w.z * v.z + w.w * v.w;
        }
        s += bq[t];
        sqf[t] = s;
        g_qf[t] = s;
    }
    __syncthreads();
    const float scale = 0.08838834764831845f; // 1/sqrt(128)
    for (int f = t; f < HH * DD; f += 128) {
        int h = f >> 7, j = f & 127;
        float acc = 0.f;
#pragma unroll
        for (int dh = 0; dh < 32; dh++)
            acc += sqf[h * 32 + dh] * Wk[(h * 32 + dh) * DD + j];
        g_a[f] = acc * scale;
    }
    if (t < HH) {
        float acc = 0.f;
#pragma unroll
        for (int dh = 0; dh < 32; dh++)
            acc += sqf[t * 32 + dh] * bk[t * 32 + dh];
        g_c[t] = acc * scale;
    }
}

// ---------------- side stream: hist/deg ----------------
__global__ void k_hist(const int* __restrict__ zone, int N,
                       const int* __restrict__ edst, int E) {
    int i = blockIdx.x * blockDim.x + threadIdx.x;
    if (i < N) {
        int c = (i >> 8) & (NCPY - 1);
        atomicAdd(&g_cnt32[c * RNUM + zone[i]], 1);
    }
    if (i < E) atomicAdd(&g_deg[edst[i]], 1);
}

// ---------------- side stream: scan + cursor bases + dis + reset ----------------
__global__ void k_scan() {
    __shared__ int sbuf[2][2048];
    int t = threadIdx.x; // 1024
    for (int k = 0; k < 2; k++) {
        int r = t + k * 1024;
        int tot = 0;
        if (r < RNUM)
            for (int c = 0; c < NCPY; c++) tot += g_cnt32[c * RNUM + r];
        sbuf[0][r] = tot;
    }
    __syncthreads();
    int src = 0;
    for (int off = 1; off < 2048; off <<= 1) {
        for (int k = 0; k < 2; k++) {
            int i = t + k * 1024;
            int v = sbuf[src][i];
            if (i >= off) v += sbuf[src][i - off];
            sbuf[1 - src][i] = v;
        }
        __syncthreads();
        src ^= 1;
    }
    for (int k = 0; k < 2; k++) {
        int r = t + k * 1024;
        if (r <= RNUM) g_starts[r] = (r == 0) ? 0 : sbuf[src][r - 1];
        if (r < RNUM) {
            int run = (r == 0) ? 0 : sbuf[src][r - 1];
            for (int c = 0; c < NCPY; c++) {
                int v = g_cnt32[c * RNUM + r];
                g_cur32[c * RNUM + r] = run;
                run += v;
                g_cnt32[c * RNUM + r] = 0;
            }
            g_dis[r] = rsqrtf((float)(g_deg[r] + 1));
            g_deg[r] = 0;
        }
    }
}

__global__ void k_scatter(const int* __restrict__ zone, int N) {
    int i = blockIdx.x * blockDim.x + threadIdx.x;
    if (i < N) {
        int z = zone[i];
        int c = (i >> 8) & (NCPY - 1);
        int pos = atomicAdd(&g_cur32[c * RNUM + z], 1);
        g_idx[pos] = i;
    }
}

// ---------------- main stream: coalesced exp-scores over x ----------------
__global__ __launch_bounds__(256) void k_scores(const float* __restrict__ x, int N, int GB) {
    int bid = blockIdx.x, t = threadIdx.x;
    __shared__ __align__(16) float4 sa4[HH * 32];
    __shared__ float sc[HH];
    for (int i = t; i < HH * DD; i += 256) ((float*)sa4)[i] = g_a[i];
    if (t < HH) sc[t] = g_c[t];
    __syncthreads();

    int warp = t >> 5, lane = t & 31, sub = lane >> 3, sl = lane & 7;
    for (int chunk = bid; chunk * 32 < N; chunk += GB) {
        int row = chunk * 32 + warp * 4 + sub;
        bool ok = row < N;
        int rowc = ok ? row : 0;
        const float4* xr = (const float4*)(x + (size_t)rowc * DD);
        float p0 = 0.f, p1 = 0.f, p2 = 0.f, p3 = 0.f;
#pragma unroll
        for (int k = 0; k < 4; k++) {
            float4 xv = xr[sl * 4 + k];
            float4 a0 = sa4[0 * 32 + sl * 4 + k];
            float4 a1 = sa4[1 * 32 + sl * 4 + k];
            float4 a2 = sa4[2 * 32 + sl * 4 + k];
            float4 a3 = sa4[3 * 32 + sl * 4 + k];
            p0 += xv.x * a0.x + xv.y * a0.y + xv.z * a0.z + xv.w * a0.w;
            p1 += xv.x * a1.x + xv.y * a1.y + xv.z * a1.z + xv.w * a1.w;
            p2 += xv.x * a2.x + xv.y * a2.y + xv.z * a2.z + xv.w * a2.w;
            p3 += xv.x * a3.x + xv.y * a3.y + xv.z * a3.z + xv.w * a3.w;
        }
#pragma unroll
        for (int off = 1; off < 8; off <<= 1) {
            p0 += __shfl_xor_sync(0xffffffffu, p0, off);
            p1 += __shfl_xor_sync(0xffffffffu, p1, off);
            p2 += __shfl_xor_sync(0xffffffffu, p2, off);
            p3 += __shfl_xor_sync(0xffffffffu, p3, off);
        }
        if (ok && sl == 0) {
            float4 e;
            e.x = __expf(p0 + sc[0]);
            e.y = __expf(p1 + sc[1]);
            e.z = __expf(p2 + sc[2]);
            e.w = __expf(p3 + sc[3]);
            g_e4[row] = e;
        }
    }
}

// ---------------- region weighted-sum: warp-pair split (2 heads/warp) ----------------
__global__ __launch_bounds__(256, 6) void k_region(const float* __restrict__ x) {
    int r = blockIdx.x;
    int base = g_starts[r];
    int cnt = g_starts[r + 1] - base;
    if (cnt > MAXM) cnt = MAXM;
    int t = threadIdx.x;

    if (cnt == 0) {
        for (int o = t; o < HH * DD; o += 256) g_Px[r * (HH * DD) + o] = 0.f;
        return;
    }

    __shared__ int   sidx[MAXM];                    // 3 KB
    __shared__ __align__(16) float4 se[MAXM];       // 12 KB (exp-scores staged)
    __shared__ __align__(16) float red[8 * 2 * DD]; // 8 KB
    __shared__ float sden[8 * 2];
    __shared__ float sinv[HH];

    for (int i = t; i < cnt; i += 256) {
        int n = g_idx[base + i];
        sidx[i] = n;
        se[i] = __ldg(&g_e4[n]);
    }
    __syncthreads();

    int warp = t >> 5, lane = t & 31;
    int pr = warp & 3;        // member lane: stride 4
    int hp = warp >> 2;       // 0 -> heads 0,1 ; 1 -> heads 2,3
    const float2* ep = ((const float2*)se) + hp;    // ep[2*i] = (e[h0], e[h0+1])

    float4 acc0 = make_float4(0.f, 0.f, 0.f, 0.f), acc1 = acc0;
    float d0 = 0.f, d1 = 0.f;

    int i = pr;
    for (; i + 4 < cnt; i += 8) {
        int n0 = sidx[i], n1 = sidx[i + 4];
        float4 x0 = __ldg((const float4*)(x + (size_t)n0 * DD) + lane);
        float4 x1 = __ldg((const float4*)(x + (size_t)n1 * DD) + lane);
        float2 e0 = ep[2 * i];
        float2 e1 = ep[2 * (i + 4)];
        acc0.x += e0.x * x0.x; acc0.y += e0.x * x0.y; acc0.z += e0.x * x0.z; acc0.w += e0.x * x0.w;
        acc1.x += e0.y * x0.x; acc1.y += e0.y * x0.y; acc1.z += e0.y * x0.z; acc1.w += e0.y * x0.w;
        d0 += e0.x; d1 += e0.y;
        acc0.x += e1.x * x1.x; acc0.y += e1.x * x1.y; acc0.z += e1.x * x1.z; acc0.w += e1.x * x1.w;
        acc1.x += e1.y * x1.x; acc1.y += e1.y * x1.y; acc1.z += e1.y * x1.z; acc1.w += e1.y * x1.w;
        d0 += e1.x; d1 += e1.y;
    }
    for (; i < cnt; i += 4) {
        int n = sidx[i];
        float4 xv = __ldg((const float4*)(x + (size_t)n * DD) + lane);
        float2 e = ep[2 * i];
        acc0.x += e.x * xv.x; acc0.y += e.x * xv.y; acc0.z += e.x * xv.z; acc0.w += e.x * xv.w;
        acc1.x += e.y * xv.x; acc1.y += e.y * xv.y; acc1.z += e.y * xv.z; acc1.w += e.y * xv.w;
        d0 += e.x; d1 += e.y;
    }

    ((float4*)(red + (warp * 2 + 0) * DD))[lane] = acc0;
    ((float4*)(red + (warp * 2 + 1) * DD))[lane] = acc1;
    if (lane == 0) { sden[warp * 2 + 0] = d0; sden[warp * 2 + 1] = d1; }
    __syncthreads();

    // head h -> warps (h>>1)*4 + {0..3}, slot hh = h&1
    if (t < HH) {
        int wb = (t >> 1) * 4, hh = t & 1;
        float s = sden[(wb + 0) * 2 + hh] + sden[(wb + 1) * 2 + hh]
                + sden[(wb + 2) * 2 + hh] + sden[(wb + 3) * 2 + hh];
        sinv[t] = 1.f / s;
    }
    __syncthreads();
    for (int o = t; o < HH * DD; o += 256) {
        int h = o >> 7, d = o & 127;
        int wb = (h >> 1) * 4, hh = h & 1;
        float s = red[((wb + 0) * 2 + hh) * DD + d] + red[((wb + 1) * 2 + hh) * DD + d]
                + red[((wb + 2) * 2 + hh) * DD + d] + red[((wb + 3) * 2 + hh) * DD + d];
        g_Px[r * (HH * DD) + o] = s * sinv[h];
    }
}

// ---------------- fused dense epilogue ----------------
__global__ __launch_bounds__(512) void k_epi(
    const float* __restrict__ Wv, const float* __restrict__ bv,
    const float* __restrict__ Wo, const float* __restrict__ bo,
    const float* __restrict__ Wg, const float* __restrict__ bg,
    float* __restrict__ out) {
    int rb = blockIdx.x * 16;
    __shared__ __align__(16) float sPx[16 * 512];
    __shared__ __align__(16) float sA[16 * XST];
    __shared__ __align__(16) float sB[16 * XST];
    __shared__ float sqf[DD];
    __shared__ float sflag[16];
    int t = threadIdx.x;

    for (int i = t; i < 16 * 512; i += 512) sPx[i] = g_Px[rb * 512 + i];
    if (t < DD) sqf[t] = g_qf[t];
    if (t < 16) sflag[t] = (g_starts[rb + t + 1] > g_starts[rb + t]) ? 1.f : 0.f;
    __syncthreads();

    int d = t & 127, rg = t >> 7;
    int h = d >> 5;
    {
        const float4* wv4 = (const float4*)(Wv + d * DD);
        float o0 = 0.f, o1 = 0.f, o2 = 0.f, o3 = 0.f;
#pragma unroll 8
        for (int j = 0; j < 32; j++) {
            float4 w = wv4[j];
            float4 p0 = ((const float4*)(sPx + (rg * 4 + 0) * 512 + h * DD))[j];
            float4 p1 = ((const float4*)(sPx + (rg * 4 + 1) * 512 + h * DD))[j];
            float4 p2 = ((const float4*)(sPx + (rg * 4 + 2) * 512 + h * DD))[j];
            float4 p3 = ((const float4*)(sPx + (rg * 4 + 3) * 512 + h * DD))[j];
            o0 += w.x * p0.x + w.y * p0.y + w.z * p0.z + w.w * p0.w;
            o1 += w.x * p1.x + w.y * p1.y + w.z * p1.z + w.w * p1.w;
            o2 += w.x * p2.x + w.y * p2.y + w.z * p2.z + w.w * p2.w;
            o3 += w.x * p3.x + w.y * p3.y + w.z * p3.z + w.w * p3.w;
        }
        float bvd = bv[d], qfd = sqf[d];
        sA[(rg * 4 + 0) * XST + d] = qfd + (o0 + bvd) * sflag[rg * 4 + 0];
        sA[(rg * 4 + 1) * XST + d] = qfd + (o1 + bvd) * sflag[rg * 4 + 1];
        sA[(rg * 4 + 2) * XST + d] = qfd + (o2 + bvd) * sflag[rg * 4 + 2];
        sA[(rg * 4 + 3) * XST + d] = qfd + (o3 + bvd) * sflag[rg * 4 + 3];
    }
    __syncthreads();
    {
        const float4* wo4 = (const float4*)(Wo + d * DD);
        float o0 = 0.f, o1 = 0.f, o2 = 0.f, o3 = 0.f;
#pragma unroll 8
        for (int j = 0; j < 32; j++) {
            float4 w = wo4[j];
            float4 p0 = ((const float4*)(sA + (rg * 4 + 0) * XST))[j];
            float4 p1 = ((const float4*)(sA + (rg * 4 + 1) * XST))[j];
            float4 p2 = ((const float4*)(sA + (rg * 4 + 2) * XST))[j];
            float4 p3 = ((const float4*)(sA + (rg * 4 + 3) * XST))[j];
            o0 += w.x * p0.x + w.y * p0.y + w.z * p0.z + w.w * p0.w;
            o1 += w.x * p1.x + w.y * p1.y + w.z * p1.z + w.w * p1.w;
            o2 += w.x * p2.x + w.y * p2.y + w.z * p2.z + w.w * p2.w;
            o3 += w.x * p3.x + w.y * p3.y + w.z * p3.z + w.w * p3.w;
        }
        float bod = bo[d];
        sB[(rg * 4 + 0) * XST + d] = sA[(rg * 4 + 0) * XST + d] + fmaxf(o0 + bod, 0.f);
        sB[(rg * 4 + 1) * XST + d] = sA[(rg * 4 + 1) * XST + d] + fmaxf(o1 + bod, 0.f);
        sB[(rg * 4 + 2) * XST + d] = sA[(rg * 4 + 2) * XST + d] + fmaxf(o2 + bod, 0.f);
        sB[(rg * 4 + 3) * XST + d] = sA[(rg * 4 + 3) * XST + d] + fmaxf(o3 + bod, 0.f);
    }
    __syncthreads();
    {
        const float4* wg4 = (const float4*)(Wg + d * DD);
        float o0 = 0.f, o1 = 0.f, o2 = 0.f, o3 = 0.f;
#pragma unroll 8
        for (int j = 0; j < 32; j++) {
            float4 w = wg4[j];
            float4 p0 = ((const float4*)(sB + (rg * 4 + 0) * XST))[j];
            float4 p1 = ((const float4*)(sB + (rg * 4 + 1) * XST))[j];
            float4 p2 = ((const float4*)(sB + (rg * 4 + 2) * XST))[j];
            float4 p3 = ((const float4*)(sB + (rg * 4 + 3) * XST))[j];
            o0 += w.x * p0.x + w.y * p0.y + w.z * p0.z + w.w * p0.w;
            o1 += w.x * p1.x + w.y * p1.y + w.z * p1.z + w.w * p1.w;
            o2 += w.x * p2.x + w.y * p2.y + w.z * p2.z + w.w * p2.w;
            o3 += w.x * p3.x + w.y * p3.y + w.z * p3.z + w.w * p3.w;
        }
        float bgd = bg[d];
#pragma unroll
        for (int k = 0; k < 4; k++) {
            int rr = rg * 4 + k;
            float hg = (k == 0) ? o0 : (k == 1) ? o1 : (k == 2) ? o2 : o3;
            int r = rb + rr;
            g_hg[r * DD + d] = hg;
            float dis = g_dis[r];
            out[r * DD + d] = bgd + dis * dis * hg;
        }
    }
}

// ---------------- GCN edges + PReLU ----------------
__global__ void k_gcn_edges(const int* __restrict__ src, const int* __restrict__ dst,
                            int E, float* __restrict__ out) {
    int tid = blockIdx.x * blockDim.x + threadIdx.x;
    int e = tid >> 5, lane = tid & 31;
    if (e < E) {
        int s = src[e], d = dst[e];
        float norm = g_dis[s] * g_dis[d];
        float4 hv = ((const float4*)g_hg)[s * 32 + lane];
        float* ob = out + d * DD + lane * 4;
        atomicAdd(ob + 0, norm * hv.x);
        atomicAdd(ob + 1, norm * hv.y);
        atomicAdd(ob + 2, norm * hv.z);
        atomicAdd(ob + 3, norm * hv.w);
    }
}

__global__ void k_prelu(float* __restrict__ out, const float* __restrict__ pw) {
    int i = blockIdx.x * blockDim.x + threadIdx.x;
    if (i < RNUM * DD) {
        float v = out[i];
        out[i] = (v > 0.f) ? v : pw[i & 127] * v;
    }
}

// ---------------- launch: fork-join overlap of sort chain vs score chain ----------------
extern "C" void kernel_launch(void* const* d_in, const int* in_sizes, int n_in,
                              void* d_out, int out_size) {
    const float* x    = (const float*)d_in[0];
    const int*   zone = (const int*)d_in[1];
    const int*   adj  = (const int*)d_in[2];
    const float* S    = (const float*)d_in[3];
    const float* Wq   = (const float*)d_in[4];
    const float* bq   = (const float*)d_in[5];
    const float* Wk   = (const float*)d_in[6];
    const float* bk   = (const float*)d_in[7];
    const float* Wv   = (const float*)d_in[8];
    const float* bv   = (const float*)d_in[9];
    const float* Wo   = (const float*)d_in[10];
    const float* bo   = (const float*)d_in[11];
    const float* Wg   = (const float*)d_in[12];
    const float* bg   = (const float*)d_in[13];
    const float* pw   = (const float*)d_in[14];
    float* out = (float*)d_out;

    int N = in_sizes[0] / DD;
    int E = in_sizes[2] / 2;
    const int* esrc = adj;
    const int* edst = adj + E;
    int NE = (N > E) ? N : E;

    static cudaStream_t s1 = nullptr;
    static cudaEvent_t evF = nullptr, evJ = nullptr;
    if (!s1) {
        cudaStreamCreateWithFlags(&s1, cudaStreamNonBlocking);
        cudaEventCreateWithFlags(&evF, cudaEventDisableTiming);
        cudaEventCreateWithFlags(&evJ, cudaEventDisableTiming);
    }

    // fork: side stream does the sort chain
    cudaEventRecord(evF, 0);
    cudaStreamWaitEvent(s1, evF, 0);
    k_hist<<<(NE + 255) / 256, 256, 0, s1>>>(zone, N, edst, E);
    k_scan<<<1, 1024, 0, s1>>>();
    k_scatter<<<(N + 255) / 256, 256, 0, s1>>>(zone, N);
    cudaEventRecord(evJ, s1);

    // main stream: prep + scores (independent of sort chain)
    k_prep<<<1, 128>>>(S, Wq, bq, Wk, bk);
    k_scores<<<2368, 256>>>(x, N, 2368);

    // join
    cudaStreamWaitEvent(0, evJ, 0);
    k_region<<<RNUM, 256>>>(x);
    k_epi<<<RNUM / 16, 512>>>(Wv, bv, Wo, bo, Wg, bg, out);
    k_gcn_edges<<<(E * 32 + 255) / 256, 256>>>(esrc, edst, E, out);
    k_prelu<<<(RNUM * DD + 255) / 256, 256>>>(out, pw);
}